// round 11
// baseline (speedup 1.0000x reference)
#include <cuda_runtime.h>
#include <math.h>

#define NN    50000
#define EDG   800000
#define DIN   256
#define HH    4
#define DHD   64
#define HD    256
#define NPH   12500          // NN/HH: physical rows per head in the reshape
#define ETOT  (EDG + NN)     // edges + self loops
#define MAXN_F 0.996f
#define MINN   1e-15f
#define ATANH_CLIP (1.0f - 1e-7f)

// -------- device scratch --------
__device__ __align__(16) float g_scaleA[NN];
__device__ __align__(16) float g_v[NN * HD];
__device__ __align__(16) float g_glx[HH * NN * DHD];   // logx in [H][N][DH]
__device__ __align__(16) float g_si[HH * NN];
__device__ __align__(16) float g_sj[HH * NN];
__device__ __align__(16) float g_hb[HD];
__device__ __align__(16) float g_acc[HH * NN * DHD];   // unnormalized aggregation
__device__ float    g_z[HH * NN];                      // softmax partition
__device__ unsigned g_mx[HH * NN];                     // encoded running max
__device__ float    g_y2[1];
__device__ int      g_mode;    // edge dtype: 0=i32 1=i64 2=f32 3=f64
__device__ int      g_bsel;    // which 256-vec is b_lin
__device__ unsigned g_eqflag;  // >0 -> planar [2,E]; 0 -> interleaved [E,2]

__device__ __forceinline__ float warp_sum(float v) {
    #pragma unroll
    for (int o = 16; o > 0; o >>= 1) v += __shfl_xor_sync(0xffffffffu, v, o);
    return v;
}

// monotonic float<->uint encoding for atomicMax over signed floats
__device__ __forceinline__ unsigned enc_f(float f) {
    unsigned b = __float_as_uint(f);
    return (b & 0x80000000u) ? ~b : (b | 0x80000000u);
}
__device__ __forceinline__ float dec_f(unsigned u) {
    return __uint_as_float((u & 0x80000000u) ? (u & 0x7FFFFFFFu) : ~u);
}

// ============================================================================
// zero all per-launch accumulators
// ============================================================================
__global__ void k_zeroall() {
    int i = blockIdx.x * blockDim.x + threadIdx.x;
    if (i < HH * NN * DHD) g_acc[i] = 0.f;
    if (i < HH * NN) { g_z[i] = 0.f; g_mx[i] = 0u; }
    if (i == 0) g_eqflag = 0u;
}

// ============================================================================
// edge dtype detection (layout-independent)
// ============================================================================
__global__ void k_detect(const unsigned int* __restrict__ p) {
    int t = threadIdx.x;
    unsigned ace = 0, aco = 0, amax = 0;
    for (int i = t; i < 1024; i += 32) {
        unsigned e = p[2 * i], o = p[2 * i + 1];
        ace |= e; aco |= o;
        unsigned mx = e > o ? e : o;
        if (mx > amax) amax = mx;
    }
    #pragma unroll
    for (int o = 16; o > 0; o >>= 1) {
        ace |= __shfl_xor_sync(0xffffffffu, ace, o);
        aco |= __shfl_xor_sync(0xffffffffu, aco, o);
        unsigned other = __shfl_xor_sync(0xffffffffu, amax, o);
        if (other > amax) amax = other;
    }
    if (t == 0) {
        int mode;
        if (aco == 0u)       mode = 1;
        else if (ace == 0u)  mode = 3;
        else                 mode = (amax > (1u << 20)) ? 2 : 0;
        g_mode = mode;
    }
}

__device__ __forceinline__ int edge_raw(const void* p, long long idx) {
    int m = g_mode;
    if (m == 0) return ((const int*)p)[idx];
    if (m == 1) return (int)((const long long*)p)[idx];
    if (m == 2) return (int)((const float*)p)[idx];
    return (int)((const double*)p)[idx];
}

// ============================================================================
// layout detection: dataset guarantees src != dst per edge. In [E,2] layout
// aligned pairs (2i,2i+1) are (src_i,dst_i): never equal. In [2,E] they are
// independent randoms: ~16 expected collisions. Any collision => planar [2,E].
// ============================================================================
__global__ void k_detlay(const void* __restrict__ eiv) {
    int i = blockIdx.x * blockDim.x + threadIdx.x;
    if (i < EDG) {
        int a = edge_raw(eiv, 2LL * i);
        int b = edge_raw(eiv, 2LL * i + 1);
        if (a == b) atomicOr(&g_eqflag, 1u);
    }
}

__device__ __forceinline__ int e_src(const void* p, int e) {
    return g_eqflag ? edge_raw(p, e) : edge_raw(p, 2LL * e);
}
__device__ __forceinline__ int e_dst(const void* p, int e) {
    return g_eqflag ? edge_raw(p, (long long)EDG + e) : edge_raw(p, 2LL * e + 1);
}

// ============================================================================
// hb = proj(expmap0(b_lin)); b_lin = larger-norm of the two 256-vectors
// ============================================================================
__global__ void k_hb(const float* __restrict__ bA, const float* __restrict__ bB) {
    __shared__ float redA[8], redB[8];
    int t = threadIdx.x;
    float va = bA[t], vb = bB[t];
    float sa = warp_sum(va * va);
    float sb = warp_sum(vb * vb);
    if ((t & 31) == 0) { redA[t >> 5] = sa; redB[t >> 5] = sb; }
    __syncthreads();
    float totA = 0.f, totB = 0.f;
    #pragma unroll
    for (int i = 0; i < 8; i++) { totA += redA[i]; totB += redB[i]; }
    int sel = (totA >= totB) ? 0 : 1;
    float v   = sel ? vb : va;
    float tot = sel ? totB : totA;

    float n  = sqrtf(tot);
    float nc = fmaxf(n, MINN);
    float t1 = tanhf(nc);
    float f  = t1 / nc;
    float nn = n * f;
    float s  = f * (nn > MAXN_F ? (MAXN_F / fmaxf(nn, MINN)) : 1.f);
    g_hb[t] = v * s;
    if (t == 0) { g_y2[0] = tot * s * s; g_bsel = sel; }
}

// ============================================================================
// per-row logmap0 scale for x (warp per row)
// ============================================================================
__global__ void k_rowscale(const float* __restrict__ x) {
    int row  = blockIdx.x * 4 + (threadIdx.x >> 5);
    int lane = threadIdx.x & 31;
    if (row >= NN) return;
    const float4* p = (const float4*)&x[row * DIN + lane * 8];
    float4 a = p[0], b = p[1];
    float ss = a.x*a.x + a.y*a.y + a.z*a.z + a.w*a.w
             + b.x*b.x + b.y*b.y + b.z*b.z + b.w*b.w;
    ss = warp_sum(ss);
    if (lane == 0) {
        float n  = sqrtf(ss);
        float nc = fmaxf(n, MINN);
        g_scaleA[row] = atanhf(fminf(nc, ATANH_CLIP)) / nc;
    }
}

// ============================================================================
// NAIVE GEMM (trivially correct): block = row n, thread = output feature o.
// v[n,o] = sum_k (x[n,k]*scaleA[n]) * W[o,k]
// ============================================================================
__global__ __launch_bounds__(256)
void k_gemm_naive(const float* __restrict__ x, const float* __restrict__ W) {
    __shared__ float sx[DIN];
    int n = blockIdx.x;
    int o = threadIdx.x;
    sx[o] = x[(size_t)n * DIN + o] * g_scaleA[n];
    __syncthreads();
    const float* wr = &W[(size_t)o * DIN];
    float sum = 0.f;
    #pragma unroll 8
    for (int k = 0; k < DIN; k++) sum = fmaf(sx[k], wr[k], sum);
    g_v[(size_t)n * HD + o] = sum;
}

// ============================================================================
// per-row hyperbolic chain; write logx into [H][N][DH] layout (warp per row)
// ============================================================================
__global__ void k_rowpost() {
    int row  = blockIdx.x * 4 + (threadIdx.x >> 5);
    int lane = threadIdx.x & 31;
    if (row >= NN) return;

    float v[8], hb[8];
    {
        const float4* pv = (const float4*)&g_v[(size_t)row * HD + lane * 8];
        float4 a = pv[0], b = pv[1];
        v[0]=a.x; v[1]=a.y; v[2]=a.z; v[3]=a.w; v[4]=b.x; v[5]=b.y; v[6]=b.z; v[7]=b.w;
        const float4* ph = (const float4*)&g_hb[lane * 8];
        float4 c = ph[0], d = ph[1];
        hb[0]=c.x; hb[1]=c.y; hb[2]=c.z; hb[3]=c.w; hb[4]=d.x; hb[5]=d.y; hb[6]=d.z; hb[7]=d.w;
    }

    float ssv = 0.f, dvh = 0.f;
    #pragma unroll
    for (int j = 0; j < 8; j++) { ssv = fmaf(v[j], v[j], ssv); dvh = fmaf(v[j], hb[j], dvh); }
    ssv = warp_sum(ssv);
    dvh = warp_sum(dvh);

    float nv  = sqrtf(ssv);
    float nvc = fmaxf(nv, MINN);
    float t1  = tanhf(nvc);
    float fe  = t1 / nvc;
    float nn  = nv * fe;
    float sxh = fe * (nn > MAXN_F ? (MAXN_F / fmaxf(nn, MINN)) : 1.f);

    float x2 = ssv * sxh * sxh;
    float xy = dvh * sxh;
    float y2 = g_y2[0];
    float c1 = 1.f + 2.f * xy + y2;
    float c2 = 1.f - x2;
    float invden = 1.f / fmaxf(1.f + 2.f * xy + x2 * y2, MINN);

    float r[8];
    float ssr = 0.f;
    #pragma unroll
    for (int j = 0; j < 8; j++) {
        r[j] = (c1 * sxh * v[j] + c2 * hb[j]) * invden;
        ssr = fmaf(r[j], r[j], ssr);
    }
    ssr = warp_sum(ssr);

    float nr  = sqrtf(ssr);
    float nrc = fmaxf(nr, MINN);
    float sp  = (nr > MAXN_F) ? (MAXN_F / nrc) : 1.f;
    float nf  = nr * sp;
    float nfc = fmaxf(nf, MINN);
    float g   = atanhf(fminf(nfc, ATANH_CLIP)) / nfc;
    float sl  = sp * g;

    int h    = row / NPH;
    int m    = row % NPH;
    int quad = lane >> 3;
    int d0   = (lane & 7) * 8;
    int iv   = 4 * m + quad;

    float* dst = &g_glx[((size_t)(h * NN + iv)) * DHD + d0];
    ((float4*)dst)[0] = make_float4(r[0]*sl, r[1]*sl, r[2]*sl, r[3]*sl);
    ((float4*)dst)[1] = make_float4(r[4]*sl, r[5]*sl, r[6]*sl, r[7]*sl);
}

// ============================================================================
// s_i / s_j scores: one warp per (h,i) pair
// ============================================================================
__global__ void ks_score(const float* __restrict__ att) {
    int w    = blockIdx.x * 8 + (threadIdx.x >> 5);
    int lane = threadIdx.x & 31;
    if (w >= HH * NN) return;
    int h = w / NN;
    float2 gv = *(const float2*)&g_glx[(size_t)w * DHD + 2 * lane];
    float pi = gv.x * att[h * 128 + 2 * lane]      + gv.y * att[h * 128 + 2 * lane + 1];
    float pj = gv.x * att[h * 128 + 64 + 2 * lane] + gv.y * att[h * 128 + 64 + 2 * lane + 1];
    pi = warp_sum(pi);
    pj = warp_sum(pj);
    if (lane == 0) { g_si[w] = pi; g_sj[w] = pj; }
}

// ============================================================================
// edge-parallel segment softmax (no CSR). Three passes.
// ============================================================================
__device__ __forceinline__ bool edge_sd(const void* eiv, int e, int& s, int& d) {
    if (e < EDG) {
        s = e_src(eiv, e);
        d = e_dst(eiv, e);
        return ((unsigned)s < (unsigned)NN) && ((unsigned)d < (unsigned)NN);
    }
    s = d = e - EDG;    // self loop
    return true;
}
__device__ __forceinline__ float lrelu(float a) { return a > 0.f ? a : 0.2f * a; }

__global__ void k_amax(const void* __restrict__ eiv) {
    int e = blockIdx.x * blockDim.x + threadIdx.x;
    if (e >= ETOT) return;
    int s, d;
    if (!edge_sd(eiv, e, s, d)) return;
    #pragma unroll
    for (int h = 0; h < HH; h++) {
        float a = lrelu(g_si[h * NN + d] + g_sj[h * NN + s]);
        atomicMax(&g_mx[h * NN + d], enc_f(a));
    }
}

__global__ void k_zsum(const void* __restrict__ eiv) {
    int e = blockIdx.x * blockDim.x + threadIdx.x;
    if (e >= ETOT) return;
    int s, d;
    if (!edge_sd(eiv, e, s, d)) return;
    #pragma unroll
    for (int h = 0; h < HH; h++) {
        float a = lrelu(g_si[h * NN + d] + g_sj[h * NN + s]);
        float w = expf(a - dec_f(g_mx[h * NN + d]));
        atomicAdd(&g_z[h * NN + d], w);
    }
}

// warp per edge; lane covers dims {2*lane, 2*lane+1}
__global__ __launch_bounds__(256)
void k_wacc(const void* __restrict__ eiv) {
    int e    = blockIdx.x * 8 + (threadIdx.x >> 5);
    int lane = threadIdx.x & 31;
    if (e >= ETOT) return;
    int s, d;
    if (!edge_sd(eiv, e, s, d)) return;
    #pragma unroll
    for (int h = 0; h < HH; h++) {
        float a = lrelu(g_si[h * NN + d] + g_sj[h * NN + s]);
        float w = expf(a - dec_f(g_mx[h * NN + d]));
        float2 gv = *(const float2*)&g_glx[((size_t)(h * NN + s)) * DHD + 2 * lane];
        atomicAdd(&g_acc[((size_t)(h * NN + d)) * DHD + 2 * lane],     w * gv.x);
        atomicAdd(&g_acc[((size_t)(h * NN + d)) * DHD + 2 * lane + 1], w * gv.y);
    }
}

// ============================================================================
// epilogue: output row r: head h=r/NPH, warp q -> virtual node 4*(r%NPH)+q
// ============================================================================
__global__ __launch_bounds__(128)
void k_final(const float* __restrict__ bA, const float* __restrict__ bB,
             float* __restrict__ out) {
    int r    = blockIdx.x;
    int q    = threadIdx.x >> 5;
    int lane = threadIdx.x & 31;
    __shared__ float sh_ss[4];

    const float* b_conv = g_bsel ? bA : bB;

    int h = r / NPH;
    int i = 4 * (r % NPH) + q;

    float invZ = 1.f / fmaxf(g_z[h * NN + i], MINN);
    size_t base = ((size_t)(h * NN + i)) * DHD + 2 * lane;
    float o0 = fmaxf(g_acc[base]     * invZ + b_conv[q * 64 + 2 * lane],     0.f);
    float o1 = fmaxf(g_acc[base + 1] * invZ + b_conv[q * 64 + 2 * lane + 1], 0.f);

    float ss = warp_sum(o0 * o0 + o1 * o1);
    if (lane == 0) sh_ss[q] = ss;
    __syncthreads();
    float tot = sh_ss[0] + sh_ss[1] + sh_ss[2] + sh_ss[3];

    float no  = sqrtf(tot);
    float nc  = fmaxf(no, MINN);
    float t1  = tanhf(nc);
    float f   = t1 / nc;
    float nn  = no * f;
    float s2  = f * (nn > MAXN_F ? (MAXN_F / fmaxf(nn, MINN)) : 1.f);

    *(float2*)&out[(size_t)r * HD + q * 64 + 2 * lane] = make_float2(o0 * s2, o1 * s2);
}

// ============================================================================
extern "C" void kernel_launch(void* const* d_in, const int* in_sizes, int n_in,
                              void* d_out, int out_size) {
    const float* x = 0; const void* ei = 0; const float* W = 0;
    const float* att = 0; const float* bv[2] = {0, 0}; int nb = 0;
    for (int k = 0; k < n_in; k++) {
        int sz = in_sizes[k];
        if      (sz == NN * DIN)        x   = (const float*)d_in[k];
        else if (sz == HD * DIN)        W   = (const float*)d_in[k];
        else if (sz == HH * 2 * DHD)    att = (const float*)d_in[k];
        else if (sz == HD)              { if (nb < 2) bv[nb++] = (const float*)d_in[k]; }
        else                            ei  = d_in[k];
    }
    if (!x || !ei || !W || !att || nb < 2) {
        x = (const float*)d_in[0]; ei = d_in[1]; W = (const float*)d_in[2];
        bv[0] = (const float*)d_in[3]; att = (const float*)d_in[4];
        bv[1] = (const float*)d_in[5];
    }
    float* out = (float*)d_out;

    k_zeroall<<<(HH * NN * DHD + 255) / 256, 256>>>();
    k_detect<<<1, 32>>>((const unsigned int*)ei);
    k_detlay<<<(EDG + 255) / 256, 256>>>(ei);
    k_hb<<<1, 256>>>(bv[0], bv[1]);
    k_rowscale<<<(NN + 3) / 4, 128>>>(x);
    k_gemm_naive<<<NN, 256>>>(x, W);
    k_rowpost<<<(NN + 3) / 4, 128>>>();
    ks_score<<<(HH * NN + 7) / 8, 256>>>(att);
    k_amax<<<(ETOT + 255) / 256, 256>>>(ei);
    k_zsum<<<(ETOT + 255) / 256, 256>>>(ei);
    k_wacc<<<(ETOT + 7) / 8, 256>>>(ei);
    k_final<<<NN, 128>>>(bv[0], bv[1], out);
}

// round 15
// speedup vs baseline: 18.9693x; 18.9693x over previous
#include <cuda_runtime.h>
#include <math.h>

#define NN    50000
#define EDG   800000
#define DIN   256
#define HH    4
#define DHD   64
#define HD    256
#define NPH   12500          // NN/HH: physical rows per head in the reshape
#define ETOT  (EDG + NN)     // edges + self loops
#define MAXN_F 0.996f
#define MINN   1e-15f
#define ATANH_CLIP (1.0f - 1e-7f)

// -------- device scratch --------
__device__ __align__(16) float g_scaleA[NN];
__device__ __align__(16) float g_v[NN * HD];
__device__ __align__(16) float g_glx[HH * NN * DHD];   // logx in [H][N][DH]
__device__ __align__(16) float g_si[HH * NN];
__device__ __align__(16) float g_sj[HH * NN];
__device__ __align__(16) float g_hb[HD];
__device__ float    g_y2[1];
__device__ int      g_mode;    // edge dtype: 0=i32 1=i64 2=f32 3=f64
__device__ int      g_bsel;    // which 256-vec is b_lin
__device__ unsigned g_eqflag;  // >0 -> planar [2,E]; 0 -> interleaved [E,2]
__device__ int      g_deg[NN];
__device__ int      g_off[NN + 1];
__device__ int      g_cur[NN];
__device__ int      g_csr[ETOT];

__device__ __forceinline__ float warp_sum(float v) {
    #pragma unroll
    for (int o = 16; o > 0; o >>= 1) v += __shfl_xor_sync(0xffffffffu, v, o);
    return v;
}
__device__ __forceinline__ float warp_max(float v) {
    #pragma unroll
    for (int o = 16; o > 0; o >>= 1) v = fmaxf(v, __shfl_xor_sync(0xffffffffu, v, o));
    return v;
}

// ============================================================================
// zero degree counters + flags
// ============================================================================
__global__ void k_zero() {
    int i = blockIdx.x * blockDim.x + threadIdx.x;
    if (i < NN) g_deg[i] = 0;
    if (i == 0) g_eqflag = 0u;
}

// ============================================================================
// edge dtype detection (layout-independent)
// ============================================================================
__global__ void k_detect(const unsigned int* __restrict__ p) {
    int t = threadIdx.x;
    unsigned ace = 0, aco = 0, amax = 0;
    for (int i = t; i < 1024; i += 32) {
        unsigned e = p[2 * i], o = p[2 * i + 1];
        ace |= e; aco |= o;
        unsigned mx = e > o ? e : o;
        if (mx > amax) amax = mx;
    }
    #pragma unroll
    for (int o = 16; o > 0; o >>= 1) {
        ace |= __shfl_xor_sync(0xffffffffu, ace, o);
        aco |= __shfl_xor_sync(0xffffffffu, aco, o);
        unsigned other = __shfl_xor_sync(0xffffffffu, amax, o);
        if (other > amax) amax = other;
    }
    if (t == 0) {
        int mode;
        if (aco == 0u)       mode = 1;
        else if (ace == 0u)  mode = 3;
        else                 mode = (amax > (1u << 20)) ? 2 : 0;
        g_mode = mode;
    }
}

__device__ __forceinline__ int edge_raw(const void* p, long long idx) {
    int m = g_mode;
    if (m == 0) return ((const int*)p)[idx];
    if (m == 1) return (int)((const long long*)p)[idx];
    if (m == 2) return (int)((const float*)p)[idx];
    return (int)((const double*)p)[idx];
}

// ============================================================================
// layout detection: dataset guarantees src != dst per edge. In [E,2] layout
// aligned pairs (2i,2i+1) are never equal; in [2,E] they collide ~16 times.
// ============================================================================
__global__ void k_detlay(const void* __restrict__ eiv) {
    int i = blockIdx.x * blockDim.x + threadIdx.x;
    if (i < EDG) {
        int a = edge_raw(eiv, 2LL * i);
        int b = edge_raw(eiv, 2LL * i + 1);
        if (a == b) atomicOr(&g_eqflag, 1u);
    }
}

__device__ __forceinline__ int e_src(const void* p, int e) {
    return g_eqflag ? edge_raw(p, e) : edge_raw(p, 2LL * e);
}
__device__ __forceinline__ int e_dst(const void* p, int e) {
    return g_eqflag ? edge_raw(p, (long long)EDG + e) : edge_raw(p, 2LL * e + 1);
}

// ============================================================================
// hb = proj(expmap0(b_lin)); b_lin = larger-norm of the two 256-vectors
// ============================================================================
__global__ void k_hb(const float* __restrict__ bA, const float* __restrict__ bB) {
    __shared__ float redA[8], redB[8];
    int t = threadIdx.x;
    float va = bA[t], vb = bB[t];
    float sa = warp_sum(va * va);
    float sb = warp_sum(vb * vb);
    if ((t & 31) == 0) { redA[t >> 5] = sa; redB[t >> 5] = sb; }
    __syncthreads();
    float totA = 0.f, totB = 0.f;
    #pragma unroll
    for (int i = 0; i < 8; i++) { totA += redA[i]; totB += redB[i]; }
    int sel = (totA >= totB) ? 0 : 1;
    float v   = sel ? vb : va;
    float tot = sel ? totB : totA;

    float n  = sqrtf(tot);
    float nc = fmaxf(n, MINN);
    float t1 = tanhf(nc);
    float f  = t1 / nc;
    float nn = n * f;
    float s  = f * (nn > MAXN_F ? (MAXN_F / fmaxf(nn, MINN)) : 1.f);
    g_hb[t] = v * s;
    if (t == 0) { g_y2[0] = tot * s * s; g_bsel = sel; }
}

// ============================================================================
// per-row logmap0 scale for x (warp per row)
// ============================================================================
__global__ void k_rowscale(const float* __restrict__ x) {
    int row  = blockIdx.x * 4 + (threadIdx.x >> 5);
    int lane = threadIdx.x & 31;
    if (row >= NN) return;
    const float4* p = (const float4*)&x[row * DIN + lane * 8];
    float4 a = p[0], b = p[1];
    float ss = a.x*a.x + a.y*a.y + a.z*a.z + a.w*a.w
             + b.x*b.x + b.y*b.y + b.z*b.z + b.w*b.w;
    ss = warp_sum(ss);
    if (lane == 0) {
        float n  = sqrtf(ss);
        float nc = fmaxf(n, MINN);
        g_scaleA[row] = atanhf(fminf(nc, ATANH_CLIP)) / nc;
    }
}

// ============================================================================
// GEMM v2 (structurally different, line-verifiable):
// block = TMR=32 rows x 256 cols; thread = one output column o = tid.
// x tile staged in smem; per-thread float4 walk of W row o (W = 256KB, L2-
// resident, amortized over 32 rows); broadcast LDS.128 for x; 32 reg accs.
// v[r0+i][o] = sum_k sx[i][k] * W[o][k]
// ============================================================================
#define TMR 32
__global__ __launch_bounds__(256)
void k_gemm2(const float* __restrict__ x, const float* __restrict__ W) {
    __shared__ float sx[TMR][DIN];
    int r0 = blockIdx.x * TMR;
    int o  = threadIdx.x;         // output column 0..255

    // stage x tile (scaled), coalesced; zero-pad rows beyond NN
    for (int idx = threadIdx.x; idx < TMR * DIN; idx += 256) {
        int row = idx >> 8;           // idx / 256
        int col = idx & 255;          // idx % 256
        int gr  = r0 + row;
        sx[row][col] = (gr < NN) ? x[(size_t)gr * DIN + col] * g_scaleA[gr] : 0.f;
    }
    __syncthreads();

    float acc[TMR];
    #pragma unroll
    for (int i = 0; i < TMR; i++) acc[i] = 0.f;

    const float* wr = &W[(size_t)o * DIN];
    for (int k0 = 0; k0 < DIN; k0 += 4) {
        float4 w = *(const float4*)&wr[k0];
        #pragma unroll
        for (int i = 0; i < TMR; i++) {
            float4 sv = *(const float4*)&sx[i][k0];
            acc[i] = fmaf(sv.x, w.x, fmaf(sv.y, w.y, fmaf(sv.z, w.z, fmaf(sv.w, w.w, acc[i]))));
        }
    }

    #pragma unroll
    for (int i = 0; i < TMR; i++) {
        int gr = r0 + i;
        if (gr < NN) g_v[(size_t)gr * HD + o] = acc[i];
    }
}

// ============================================================================
// per-row hyperbolic chain; write logx into [H][N][DH] layout (warp per row)
// ============================================================================
__global__ void k_rowpost() {
    int row  = blockIdx.x * 4 + (threadIdx.x >> 5);
    int lane = threadIdx.x & 31;
    if (row >= NN) return;

    float v[8], hb[8];
    {
        const float4* pv = (const float4*)&g_v[(size_t)row * HD + lane * 8];
        float4 a = pv[0], b = pv[1];
        v[0]=a.x; v[1]=a.y; v[2]=a.z; v[3]=a.w; v[4]=b.x; v[5]=b.y; v[6]=b.z; v[7]=b.w;
        const float4* ph = (const float4*)&g_hb[lane * 8];
        float4 c = ph[0], d = ph[1];
        hb[0]=c.x; hb[1]=c.y; hb[2]=c.z; hb[3]=c.w; hb[4]=d.x; hb[5]=d.y; hb[6]=d.z; hb[7]=d.w;
    }

    float ssv = 0.f, dvh = 0.f;
    #pragma unroll
    for (int j = 0; j < 8; j++) { ssv = fmaf(v[j], v[j], ssv); dvh = fmaf(v[j], hb[j], dvh); }
    ssv = warp_sum(ssv);
    dvh = warp_sum(dvh);

    float nv  = sqrtf(ssv);
    float nvc = fmaxf(nv, MINN);
    float t1  = tanhf(nvc);
    float fe  = t1 / nvc;
    float nn  = nv * fe;
    float sxh = fe * (nn > MAXN_F ? (MAXN_F / fmaxf(nn, MINN)) : 1.f);

    float x2 = ssv * sxh * sxh;
    float xy = dvh * sxh;
    float y2 = g_y2[0];
    float c1 = 1.f + 2.f * xy + y2;
    float c2 = 1.f - x2;
    float invden = 1.f / fmaxf(1.f + 2.f * xy + x2 * y2, MINN);

    float r[8];
    float ssr = 0.f;
    #pragma unroll
    for (int j = 0; j < 8; j++) {
        r[j] = (c1 * sxh * v[j] + c2 * hb[j]) * invden;
        ssr = fmaf(r[j], r[j], ssr);
    }
    ssr = warp_sum(ssr);

    float nr  = sqrtf(ssr);
    float nrc = fmaxf(nr, MINN);
    float sp  = (nr > MAXN_F) ? (MAXN_F / nrc) : 1.f;
    float nf  = nr * sp;
    float nfc = fmaxf(nf, MINN);
    float g   = atanhf(fminf(nfc, ATANH_CLIP)) / nfc;
    float sl  = sp * g;

    int h    = row / NPH;
    int m    = row % NPH;
    int quad = lane >> 3;
    int d0   = (lane & 7) * 8;
    int iv   = 4 * m + quad;

    float* dst = &g_glx[((size_t)(h * NN + iv)) * DHD + d0];
    ((float4*)dst)[0] = make_float4(r[0]*sl, r[1]*sl, r[2]*sl, r[3]*sl);
    ((float4*)dst)[1] = make_float4(r[4]*sl, r[5]*sl, r[6]*sl, r[7]*sl);
}

// ============================================================================
// s_i / s_j scores: one warp per (h,i) pair
// ============================================================================
__global__ void ks_score(const float* __restrict__ att) {
    int w    = blockIdx.x * 8 + (threadIdx.x >> 5);
    int lane = threadIdx.x & 31;
    if (w >= HH * NN) return;
    int h = w / NN;
    float2 gv = *(const float2*)&g_glx[(size_t)w * DHD + 2 * lane];
    float pi = gv.x * att[h * 128 + 2 * lane]      + gv.y * att[h * 128 + 2 * lane + 1];
    float pj = gv.x * att[h * 128 + 64 + 2 * lane] + gv.y * att[h * 128 + 64 + 2 * lane + 1];
    pi = warp_sum(pi);
    pj = warp_sum(pj);
    if (lane == 0) { g_si[w] = pi; g_sj[w] = pj; }
}

// ============================================================================
// CSR-by-dst build (layout-aware edge decode)
// ============================================================================
__global__ void k_count(const void* __restrict__ eiv) {
    int i = blockIdx.x * blockDim.x + threadIdx.x;
    if (i < EDG) {
        int d = e_dst(eiv, i);
        if ((unsigned)d < (unsigned)NN) atomicAdd(&g_deg[d], 1);
    }
}

__global__ void k_scan() {
    __shared__ int part[1024];
    int t = threadIdx.x;
    const int CH = (NN + 1023) / 1024;
    int start = t * CH;
    int sum = 0;
    for (int i = 0; i < CH; i++) {
        int idx = start + i;
        if (idx < NN) sum += g_deg[idx] + 1;
    }
    part[t] = sum;
    __syncthreads();
    for (int o = 1; o < 1024; o <<= 1) {
        int vv = (t >= o) ? part[t - o] : 0;
        __syncthreads();
        part[t] += vv;
        __syncthreads();
    }
    int run = (t == 0) ? 0 : part[t - 1];
    for (int i = 0; i < CH; i++) {
        int idx = start + i;
        if (idx < NN) {
            g_off[idx] = run;
            g_cur[idx] = run;
            run += g_deg[idx] + 1;
        }
    }
    if (t == 1023) g_off[NN] = part[1023];
}

__global__ void k_fill(const void* __restrict__ eiv) {
    int i = blockIdx.x * blockDim.x + threadIdx.x;
    if (i < EDG) {
        int s = e_src(eiv, i);
        int d = e_dst(eiv, i);
        if ((unsigned)s < (unsigned)NN && (unsigned)d < (unsigned)NN) {
            int p = atomicAdd(&g_cur[d], 1);
            if ((unsigned)p < (unsigned)ETOT) g_csr[p] = s;
        }
    } else if (i < ETOT) {
        int n = i - EDG;
        int p = atomicAdd(&g_cur[n], 1);
        if ((unsigned)p < (unsigned)ETOT) g_csr[p] = n;   // self loop
    }
}

// ============================================================================
// per-output-row softmax attention + aggregation + epilogue (CSR-based).
// Output row r: head h=r/NPH, warp q -> virtual dst node i=4*(r%NPH)+q.
// ============================================================================
__global__ __launch_bounds__(128)
void k_attn(const float* __restrict__ bA, const float* __restrict__ bB,
            float* __restrict__ out) {
    int r    = blockIdx.x;
    int q    = threadIdx.x >> 5;
    int lane = threadIdx.x & 31;
    __shared__ float sh_ss[4];

    const float* b_conv = g_bsel ? bA : bB;

    int h = r / NPH;
    int i = 4 * (r % NPH) + q;

    int beg = g_off[i];
    int end = g_off[i + 1];
    float si = g_si[h * NN + i];
    const float* sj = &g_sj[h * NN];

    float mx = -1e30f;
    for (int e = beg + lane; e < end; e += 32) {
        int s = g_csr[e];
        float a = si + sj[s];
        a = a > 0.f ? a : 0.2f * a;
        mx = fmaxf(mx, a);
    }
    mx = warp_max(mx);

    float z = 0.f;
    for (int e = beg + lane; e < end; e += 32) {
        int s = g_csr[e];
        float a = si + sj[s];
        a = a > 0.f ? a : 0.2f * a;
        z += expf(a - mx);
    }
    z = warp_sum(z);
    float invZ = 1.f / fmaxf(z, MINN);

    float acc0 = 0.f, acc1 = 0.f;
    #pragma unroll 4
    for (int e = beg; e < end; e++) {
        int s = g_csr[e];
        float a = si + sj[s];
        a = a > 0.f ? a : 0.2f * a;
        float wt = expf(a - mx);
        float2 vv = *(const float2*)&g_glx[((size_t)(h * NN + s)) * DHD + 2 * lane];
        acc0 = fmaf(wt, vv.x, acc0);
        acc1 = fmaf(wt, vv.y, acc1);
    }

    float o0 = fmaxf(acc0 * invZ + b_conv[q * 64 + 2 * lane],     0.f);
    float o1 = fmaxf(acc1 * invZ + b_conv[q * 64 + 2 * lane + 1], 0.f);

    float ss = warp_sum(o0 * o0 + o1 * o1);
    if (lane == 0) sh_ss[q] = ss;
    __syncthreads();
    float tot = sh_ss[0] + sh_ss[1] + sh_ss[2] + sh_ss[3];

    float no  = sqrtf(tot);
    float nc  = fmaxf(no, MINN);
    float t1  = tanhf(nc);
    float f   = t1 / nc;
    float nn  = no * f;
    float s2  = f * (nn > MAXN_F ? (MAXN_F / fmaxf(nn, MINN)) : 1.f);

    *(float2*)&out[(size_t)r * HD + q * 64 + 2 * lane] = make_float2(o0 * s2, o1 * s2);
}

// ============================================================================
extern "C" void kernel_launch(void* const* d_in, const int* in_sizes, int n_in,
                              void* d_out, int out_size) {
    const float* x = 0; const void* ei = 0; const float* W = 0;
    const float* att = 0; const float* bv[2] = {0, 0}; int nb = 0;
    for (int k = 0; k < n_in; k++) {
        int sz = in_sizes[k];
        if      (sz == NN * DIN)        x   = (const float*)d_in[k];
        else if (sz == HD * DIN)        W   = (const float*)d_in[k];
        else if (sz == HH * 2 * DHD)    att = (const float*)d_in[k];
        else if (sz == HD)              { if (nb < 2) bv[nb++] = (const float*)d_in[k]; }
        else                            ei  = d_in[k];
    }
    if (!x || !ei || !W || !att || nb < 2) {
        x = (const float*)d_in[0]; ei = d_in[1]; W = (const float*)d_in[2];
        bv[0] = (const float*)d_in[3]; att = (const float*)d_in[4];
        bv[1] = (const float*)d_in[5];
    }
    float* out = (float*)d_out;

    k_zero<<<(NN + 255) / 256, 256>>>();
    k_detect<<<1, 32>>>((const unsigned int*)ei);
    k_detlay<<<(EDG + 255) / 256, 256>>>(ei);
    k_hb<<<1, 256>>>(bv[0], bv[1]);
    k_rowscale<<<(NN + 3) / 4, 128>>>(x);
    k_count<<<(EDG + 255) / 256, 256>>>(ei);
    k_scan<<<1, 1024>>>();
    k_fill<<<(ETOT + 255) / 256, 256>>>(ei);
    k_gemm2<<<(NN + TMR - 1) / TMR, 256>>>(x, W);
    k_rowpost<<<(NN + 3) / 4, 128>>>();
    ks_score<<<(HH * NN + 7) / 8, 256>>>(att);
    k_attn<<<NN, 128>>>(bv[0], bv[1], out);
}